// round 7
// baseline (speedup 1.0000x reference)
#include <cuda_runtime.h>
#include <math.h>

// Dataset-fixed shapes: r is [16, 2048, 3] fp32
#define NPTS    1024              // points per MST problem
#define NPROB   32                // independent MST problems
#define THREADS 128               // 4 warps: one per SMSP (full issue rate)
#define PPT     (NPTS / THREADS)  // 8 points per thread
#define NW      (THREADS / 32)    // 4 warps

__device__ float    g_partials[NPROB];
__device__ unsigned g_ticket;     // zero-init; last CTA resets for graph replay

__device__ __forceinline__ float warp_sum(float v) {
#pragma unroll
    for (int o = 16; o; o >>= 1) v += __shfl_xor_sync(0xffffffffu, v, o);
    return v;
}

__device__ __forceinline__ unsigned um(unsigned a, unsigned b) { return a < b ? a : b; }

// Pack: high 22 bits = float bits of h = d^2/2 (low 10 mantissa bits truncated),
// low 10 bits = point index. Unsigned order == (h, idx) order (h >= 0).
// pk values are globally unique within a problem (index embedded).
#define PK_MASK 0xFFFFFC00u

__global__ __launch_bounds__(THREADS, 1)
void topo_mst_kernel(const float* __restrict__ r, float* __restrict__ out)
{
    __shared__ float redbuf[3][NW];
    __shared__ float4 s_p0;
    __shared__ alignas(16) float4   s_win[2][NW];  // winner payload {x,y,z,q}
    __shared__ alignas(16) unsigned s_pk[2][NW];   // winner packed (h,idx)
    __shared__ bool s_last;

    const int tid  = threadIdx.x;
    const int lane = tid & 31;
    const int wid  = tid >> 5;

    const float* base = r + (size_t)blockIdx.x * NPTS * 3;

    // ---- Load (thread t owns points t, t+128, ..., t+896) ----
    float lx[PPT], ly[PPT], lz[PPT];
    float sx = 0.f, sy = 0.f, sz = 0.f;
#pragma unroll
    for (int s = 0; s < PPT; s++) {
        int i = tid + s * THREADS;
        float x = base[3 * i + 0];
        float y = base[3 * i + 1];
        float z = base[3 * i + 2];
        lx[s] = x; ly[s] = y; lz[s] = z;
        sx += x; sy += y; sz += z;
    }

    // ---- Mean ----
    sx = warp_sum(sx); sy = warp_sum(sy); sz = warp_sum(sz);
    if (lane == 0) { redbuf[0][wid] = sx; redbuf[1][wid] = sy; redbuf[2][wid] = sz; }
    __syncthreads();
    float mx = 0.f, my = 0.f, mz = 0.f;
#pragma unroll
    for (int w = 0; w < NW; w++) { mx += redbuf[0][w]; my += redbuf[1][w]; mz += redbuf[2][w]; }
    mx *= (1.0f / NPTS); my *= (1.0f / NPTS); mz *= (1.0f / NPTS);
    __syncthreads();

    // ---- Variance ----
    float vx = 0.f, vy = 0.f, vz = 0.f;
#pragma unroll
    for (int s = 0; s < PPT; s++) {
        float dx = lx[s] - mx, dy = ly[s] - my, dz = lz[s] - mz;
        vx = fmaf(dx, dx, vx); vy = fmaf(dy, dy, vy); vz = fmaf(dz, dz, vz);
    }
    vx = warp_sum(vx); vy = warp_sum(vy); vz = warp_sum(vz);
    if (lane == 0) { redbuf[0][wid] = vx; redbuf[1][wid] = vy; redbuf[2][wid] = vz; }
    __syncthreads();
    vx = 0.f; vy = 0.f; vz = 0.f;
#pragma unroll
    for (int w = 0; w < NW; w++) { vx += redbuf[0][w]; vy += redbuf[1][w]; vz += redbuf[2][w]; }
    const float inx = 1.0f / (sqrtf(vx * (1.0f / NPTS)) + 1e-8f);
    const float iny = 1.0f / (sqrtf(vy * (1.0f / NPTS)) + 1e-8f);
    const float inz = 1.0f / (sqrtf(vz * (1.0f / NPTS)) + 1e-8f);

    // ---- Normalize; q = |p|^2/2 ----
    float ql[PPT];
#pragma unroll
    for (int s = 0; s < PPT; s++) {
        float x = (lx[s] - mx) * inx;
        float y = (ly[s] - my) * iny;
        float z = (lz[s] - mz) * inz;
        lx[s] = x; ly[s] = y; lz[s] = z;
        ql[s] = 0.5f * fmaf(x, x, fmaf(y, y, z * z));
    }
    if (tid == 0) s_p0 = make_float4(lx[0], ly[0], lz[0], ql[0]);
    __syncthreads();

    // ---- Prim init (h = d^2/2 = q_s + q_j - p.pj) ----
    const float    INF_F   = __int_as_float(0x7f800000);
    const unsigned VISITED = 0xFFFFFFFFu;

    float4 p0 = s_p0;
    unsigned pk[PPT];
#pragma unroll
    for (int s = 0; s < PPT; s++) {
        float h = fmaf(-lx[s], p0.x, fmaf(-ly[s], p0.y, fmaf(-lz[s], p0.z, ql[s] + p0.w)));
        pk[s] = (__float_as_uint(h) & PK_MASK) | (unsigned)(tid + s * THREADS);
    }
    if (tid == 0) {     // root visited: INF q forces its future h = +inf
        pk[0] = VISITED;
        ql[0] = INF_F;
    }

    float total = 0.0f;   // accumulates h (= d^2/2); doubled at the end
    for (int it = 0; it < NPTS - 1; ++it) {
        const int buf = it & 1;

        // ---- thread-local argmin WITH payload (SEL tree, shallow at PPT=8) ----
        unsigned m01 = um(pk[0], pk[1]), m23 = um(pk[2], pk[3]);
        unsigned m45 = um(pk[4], pk[5]), m67 = um(pk[6], pk[7]);
        unsigned lm  = um(um(m01, m23), um(m45, m67));

        unsigned wm = __reduce_min_sync(0xffffffffu, lm);

        // winner lane (exactly one: pk unique) finds its slot & ships payload
        if (lm == wm) {
            int bs = 0;
#pragma unroll
            for (int s = 1; s < PPT; s++) if (pk[s] == wm) bs = s;
            s_win[buf][wid] = make_float4(lx[bs], ly[bs], lz[bs], ql[bs]);
            s_pk[buf][wid]  = wm;
        }
        __syncthreads();   // one barrier per iteration (double-buffered)

        // ---- cross-warp tournament: independent LDS + 3-level SEL ----
        uint4 pkv = *reinterpret_cast<const uint4*>(s_pk[buf]);
        float4 a0 = s_win[buf][0], a1 = s_win[buf][1];
        float4 a2 = s_win[buf][2], a3 = s_win[buf][3];

        bool b0 = pkv.y < pkv.x;
        unsigned v0 = b0 ? pkv.y : pkv.x;
        float e0x = b0 ? a1.x : a0.x, e0y = b0 ? a1.y : a0.y;
        float e0z = b0 ? a1.z : a0.z, e0q = b0 ? a1.w : a0.w;
        bool b1 = pkv.w < pkv.z;
        unsigned v1 = b1 ? pkv.w : pkv.z;
        float e1x = b1 ? a3.x : a2.x, e1y = b1 ? a3.y : a2.y;
        float e1z = b1 ? a3.z : a2.z, e1q = b1 ? a3.w : a2.w;
        bool c = v1 < v0;
        unsigned g = c ? v1 : v0;
        float gx = c ? e1x : e0x, gy = c ? e1y : e0y;
        float gz = c ? e1z : e0z, gq = c ? e1q : e0q;

        total += __uint_as_float(g & PK_MASK);

        // mark visited: exactly the slot whose pk equals g (unique)
#pragma unroll
        for (int s = 0; s < PPT; s++) {
            if (pk[s] == g) { pk[s] = VISITED; ql[s] = INF_F; }
        }

        // relax: h = q_s + q_j - p.pj  (coords & q_j arrived with the min)
#pragma unroll
        for (int s = 0; s < PPT; s++) {
            float h = fmaf(-lx[s], gx, fmaf(-ly[s], gy, fmaf(-lz[s], gz, ql[s] + gq)));
            unsigned cand = (__float_as_uint(h) & PK_MASK) | (unsigned)(tid + s * THREADS);
            pk[s] = um(pk[s], cand);
        }
    }

    // ---- deterministic finalize in the last-arriving CTA ----
    if (tid == 0) {
        g_partials[blockIdx.x] = total * 2.0f;   // h -> d^2
        __threadfence();
        unsigned t = atomicAdd(&g_ticket, 1u);
        s_last = (t == NPROB - 1);
    }
    __syncthreads();
    if (s_last && tid == 0) {
        __threadfence();
        float acc = 0.0f;
#pragma unroll
        for (int p = 0; p < NPROB; p++) acc += g_partials[p];
        out[0] = acc * (1.0f / NPROB);
        g_ticket = 0;   // reset for next graph replay
    }
}

extern "C" void kernel_launch(void* const* d_in, const int* in_sizes, int n_in,
                              void* d_out, int out_size)
{
    const float* r = (const float*)d_in[0];
    float* out = (float*)d_out;
    topo_mst_kernel<<<NPROB, THREADS>>>(r, out);
}

// round 8
// speedup vs baseline: 1.1824x; 1.1824x over previous
#include <cuda_runtime.h>
#include <math.h>

// Dataset-fixed shapes: r is [16, 2048, 3] fp32
#define NPTS    1024              // points per MST problem
#define NPROB   32                // independent MST problems
#define THREADS 128               // 4 warps: one per SMSP (full issue rate)
#define PPT     (NPTS / THREADS)  // 8 points per thread
#define NW      (THREADS / 32)    // 4 warps

__device__ float    g_partials[NPROB];
__device__ unsigned g_ticket;     // zero-init; last CTA resets for graph replay

__device__ __forceinline__ float warp_sum(float v) {
#pragma unroll
    for (int o = 16; o; o >>= 1) v += __shfl_xor_sync(0xffffffffu, v, o);
    return v;
}

__device__ __forceinline__ unsigned um(unsigned a, unsigned b) { return a < b ? a : b; }

// Pack: high 22 bits = float bits of h = d^2/2 (low 10 mantissa bits truncated),
// low 10 bits = point index. Unsigned order == (h, idx) order (h >= 0).
// pk values are globally unique within a problem (index embedded), so every
// thread's local min lm is unique too -> exactly one lane matches the REDUX min.
#define PK_MASK 0xFFFFFC00u

__global__ __launch_bounds__(THREADS, 1)
void topo_mst_kernel(const float* __restrict__ r, float* __restrict__ out)
{
    __shared__ float redbuf[3][NW];
    __shared__ float4 s_p0;
    __shared__ alignas(16) float4   s_win[2][NW];  // winner payload {x,y,z,q}
    __shared__ alignas(16) unsigned s_pk[2][NW];   // winner packed (h,idx)
    __shared__ alignas(16) float4   s_dumpw;       // write sink for non-winners
    __shared__ unsigned             s_dumpp;
    __shared__ bool s_last;

    const int tid  = threadIdx.x;
    const int lane = tid & 31;
    const int wid  = tid >> 5;

    const float* base = r + (size_t)blockIdx.x * NPTS * 3;

    // ---- Load (thread t owns points t, t+128, ..., t+896) ----
    float lx[PPT], ly[PPT], lz[PPT];
    float sx = 0.f, sy = 0.f, sz = 0.f;
#pragma unroll
    for (int s = 0; s < PPT; s++) {
        int i = tid + s * THREADS;
        float x = base[3 * i + 0];
        float y = base[3 * i + 1];
        float z = base[3 * i + 2];
        lx[s] = x; ly[s] = y; lz[s] = z;
        sx += x; sy += y; sz += z;
    }

    // ---- Mean ----
    sx = warp_sum(sx); sy = warp_sum(sy); sz = warp_sum(sz);
    if (lane == 0) { redbuf[0][wid] = sx; redbuf[1][wid] = sy; redbuf[2][wid] = sz; }
    __syncthreads();
    float mx = 0.f, my = 0.f, mz = 0.f;
#pragma unroll
    for (int w = 0; w < NW; w++) { mx += redbuf[0][w]; my += redbuf[1][w]; mz += redbuf[2][w]; }
    mx *= (1.0f / NPTS); my *= (1.0f / NPTS); mz *= (1.0f / NPTS);
    __syncthreads();

    // ---- Variance ----
    float vx = 0.f, vy = 0.f, vz = 0.f;
#pragma unroll
    for (int s = 0; s < PPT; s++) {
        float dx = lx[s] - mx, dy = ly[s] - my, dz = lz[s] - mz;
        vx = fmaf(dx, dx, vx); vy = fmaf(dy, dy, vy); vz = fmaf(dz, dz, vz);
    }
    vx = warp_sum(vx); vy = warp_sum(vy); vz = warp_sum(vz);
    if (lane == 0) { redbuf[0][wid] = vx; redbuf[1][wid] = vy; redbuf[2][wid] = vz; }
    __syncthreads();
    vx = 0.f; vy = 0.f; vz = 0.f;
#pragma unroll
    for (int w = 0; w < NW; w++) { vx += redbuf[0][w]; vy += redbuf[1][w]; vz += redbuf[2][w]; }
    const float inx = 1.0f / (sqrtf(vx * (1.0f / NPTS)) + 1e-8f);
    const float iny = 1.0f / (sqrtf(vy * (1.0f / NPTS)) + 1e-8f);
    const float inz = 1.0f / (sqrtf(vz * (1.0f / NPTS)) + 1e-8f);

    // ---- Normalize; q = |p|^2/2 ----
    float ql[PPT];
#pragma unroll
    for (int s = 0; s < PPT; s++) {
        float x = (lx[s] - mx) * inx;
        float y = (ly[s] - my) * iny;
        float z = (lz[s] - mz) * inz;
        lx[s] = x; ly[s] = y; lz[s] = z;
        ql[s] = 0.5f * fmaf(x, x, fmaf(y, y, z * z));
    }
    if (tid == 0) s_p0 = make_float4(lx[0], ly[0], lz[0], ql[0]);
    __syncthreads();

    // ---- Prim init (h = d^2/2 = q_s + q_j - p.pj) ----
    const float    INF_F   = __int_as_float(0x7f800000);
    const unsigned VISITED = 0xFFFFFFFFu;

    float4 p0 = s_p0;
    unsigned pk[PPT];
#pragma unroll
    for (int s = 0; s < PPT; s++) {
        float h = fmaf(-lx[s], p0.x, fmaf(-ly[s], p0.y, fmaf(-lz[s], p0.z, ql[s] + p0.w)));
        pk[s] = (__float_as_uint(h) & PK_MASK) | (unsigned)(tid + s * THREADS);
    }
    if (tid == 0) {     // root visited: INF q forces its future h = +inf
        pk[0] = VISITED;
        ql[0] = INF_F;
    }

    float total = 0.0f;   // accumulates h (= d^2/2); doubled at the end
    for (int it = 0; it < NPTS - 1; ++it) {
        const int buf = it & 1;

        // ---- fast lm via IMNMX tree (feeds REDUX ASAP) ----
        unsigned m01 = um(pk[0], pk[1]), m23 = um(pk[2], pk[3]);
        unsigned m45 = um(pk[4], pk[5]), m67 = um(pk[6], pk[7]);
        unsigned lm  = um(um(m01, m23), um(m45, m67));

        unsigned wm = __reduce_min_sync(0xffffffffu, lm);

        // ---- parallel coord-candidate tree (overlaps REDUX latency) ----
        bool c01 = pk[1] < pk[0];
        float ax0 = c01 ? lx[1] : lx[0], ay0 = c01 ? ly[1] : ly[0];
        float az0 = c01 ? lz[1] : lz[0], aq0 = c01 ? ql[1] : ql[0];
        bool c23 = pk[3] < pk[2];
        float ax1 = c23 ? lx[3] : lx[2], ay1 = c23 ? ly[3] : ly[2];
        float az1 = c23 ? lz[3] : lz[2], aq1 = c23 ? ql[3] : ql[2];
        bool c45 = pk[5] < pk[4];
        float ax2 = c45 ? lx[5] : lx[4], ay2 = c45 ? ly[5] : ly[4];
        float az2 = c45 ? lz[5] : lz[4], aq2 = c45 ? ql[5] : ql[4];
        bool c67 = pk[7] < pk[6];
        float ax3 = c67 ? lx[7] : lx[6], ay3 = c67 ? ly[7] : ly[6];
        float az3 = c67 ? lz[7] : lz[6], aq3 = c67 ? ql[7] : ql[6];
        bool d0 = m23 < m01;
        float bx0 = d0 ? ax1 : ax0, by0 = d0 ? ay1 : ay0;
        float bz0 = d0 ? az1 : az0, bq0 = d0 ? aq1 : aq0;
        bool d1 = m67 < m45;
        float bx1 = d1 ? ax3 : ax2, by1 = d1 ? ay3 : ay2;
        float bz1 = d1 ? az3 : az2, bq1 = d1 ? aq3 : aq2;
        bool e0 = um(m45, m67) < um(m01, m23);
        float cx = e0 ? bx1 : bx0, cy = e0 ? by1 : by0;
        float cz = e0 ? bz1 : bz0, cq = e0 ? bq1 : bq0;

        // ---- branch-free ship: winner lane -> real slot, others -> dump ----
        bool win = (lm == wm);          // exactly one lane (lm values distinct)
        float4*   wdst = win ? &s_win[buf][wid] : &s_dumpw;
        unsigned* pdst = win ? &s_pk[buf][wid]  : &s_dumpp;
        *wdst = make_float4(cx, cy, cz, cq);
        *pdst = wm;
        __syncthreads();   // one barrier per iteration (double-buffered)

        // ---- cross-warp tournament: 5 parallel LDS.128 + 2-level SEL ----
        uint4 pkv = *reinterpret_cast<const uint4*>(s_pk[buf]);
        float4 a0 = s_win[buf][0], a1 = s_win[buf][1];
        float4 a2 = s_win[buf][2], a3 = s_win[buf][3];

        bool b0 = pkv.y < pkv.x;
        unsigned v0 = b0 ? pkv.y : pkv.x;
        float e0x = b0 ? a1.x : a0.x, e0y = b0 ? a1.y : a0.y;
        float e0z = b0 ? a1.z : a0.z, e0q = b0 ? a1.w : a0.w;
        bool b1 = pkv.w < pkv.z;
        unsigned v1 = b1 ? pkv.w : pkv.z;
        float e1x = b1 ? a3.x : a2.x, e1y = b1 ? a3.y : a2.y;
        float e1z = b1 ? a3.z : a2.z, e1q = b1 ? a3.w : a2.w;
        bool cc = v1 < v0;
        unsigned g = cc ? v1 : v0;
        float gx = cc ? e1x : e0x, gy = cc ? e1y : e0y;
        float gz = cc ? e1z : e0z, gq = cc ? e1q : e0q;

        total += __uint_as_float(g & PK_MASK);

        // mark visited: exactly the slot whose pk equals g (unique)
#pragma unroll
        for (int s = 0; s < PPT; s++) {
            if (pk[s] == g) { pk[s] = VISITED; ql[s] = INF_F; }
        }

        // relax: h = q_s + q_j - p.pj  (coords & q_j arrived with the min)
#pragma unroll
        for (int s = 0; s < PPT; s++) {
            float h = fmaf(-lx[s], gx, fmaf(-ly[s], gy, fmaf(-lz[s], gz, ql[s] + gq)));
            unsigned cand = (__float_as_uint(h) & PK_MASK) | (unsigned)(tid + s * THREADS);
            pk[s] = um(pk[s], cand);
        }
    }

    // ---- deterministic finalize in the last-arriving CTA ----
    if (tid == 0) {
        g_partials[blockIdx.x] = total * 2.0f;   // h -> d^2
        __threadfence();
        unsigned t = atomicAdd(&g_ticket, 1u);
        s_last = (t == NPROB - 1);
    }
    __syncthreads();
    if (s_last && tid == 0) {
        __threadfence();
        float acc = 0.0f;
#pragma unroll
        for (int p = 0; p < NPROB; p++) acc += g_partials[p];
        out[0] = acc * (1.0f / NPROB);
        g_ticket = 0;   // reset for next graph replay
    }
}

extern "C" void kernel_launch(void* const* d_in, const int* in_sizes, int n_in,
                              void* d_out, int out_size)
{
    const float* r = (const float*)d_in[0];
    float* out = (float*)d_out;
    topo_mst_kernel<<<NPROB, THREADS>>>(r, out);
}